// round 3
// baseline (speedup 1.0000x reference)
#include <cuda_runtime.h>
#include <cstdint>

#define TMAX 1280

__device__ int g_lab[TMAX];        // normalized int32 labels
__device__ float4 g_txyxy[TMAX];   // fallback path only
__device__ float2 g_tal[TMAX];     // fallback path only

__device__ __forceinline__ float frcp(float x) {
    float r;
    asm("rcp.approx.f32 %0, %1;" : "=f"(r) : "f"(x));
    return r;
}

// Normalizes labels (int64 vs int32 autodetect) and fills fallback tables.
__global__ void setup_kernel(const float4* __restrict__ tboxes,
                             const int* __restrict__ lraw, int m) {
    __shared__ int is64;
    if (threadIdx.x == 0) is64 = 1;
    __syncthreads();
    for (int t = threadIdx.x; t < m / 2; t += blockDim.x)
        if (lraw[2 * t + 1] != 0) is64 = 0;   // benign race, single value
    __syncthreads();
    int f = is64;
    for (int j = threadIdx.x; j < m; j += blockDim.x) {
        int lab = f ? lraw[2 * j] : lraw[j];
        g_lab[j] = lab;
        float4 b = tboxes[j];
        float hw = 0.5f * b.z, hh = 0.5f * b.w;
        float4 t;
        t.x = b.x - hw; t.y = b.y - hh;
        t.z = b.x + hw; t.w = b.y + hh;
        g_txyxy[j] = t;
        float2 al;
        al.x = (t.z - t.x) * (t.w - t.y);
        al.y = __int_as_float(lab);
        g_tal[j] = al;
    }
}

// ---------------------------------------------------------------------------
// Fast path, specialized: C=91, M=1280, rows % 16 == 0.
// Block = 256 thr = 16 rows x 64 column-lanes; thread owns 4 rows x 20 steps.
// Query data lives in xyxy-only registers; L1 cost derived from xyxy diffs.
// launch_bounds(256,4) caps regs at 64 -> 4 blocks/SM -> 32 warps.
// ---------------------------------------------------------------------------
__global__ void __launch_bounds__(256, 4)
cost_kernel_fast(const float* __restrict__ scores,
                 const float4* __restrict__ boxes,
                 const float4* __restrict__ tboxes,
                 float* __restrict__ out) {
    constexpr int C = 91;
    constexpr int M = 1280;
    constexpr int NJ = M / 64;   // 20

    int tid = threadIdx.x;
    int tx = tid & 63;
    int ty = tid >> 6;
    int row0 = blockIdx.x * 16 + ty * 4;

    float qx0[4], qy0[4], qx1[4], qy1[4], qa[4];

#pragma unroll
    for (int k = 0; k < 4; k++) {
        float4 bb = __ldg(boxes + row0 + k);
        float hw = 0.5f * bb.z, hh = 0.5f * bb.w;
        qx0[k] = bb.x - hw; qy0[k] = bb.y - hh;
        qx1[k] = bb.x + hw; qy1[k] = bb.y + hh;
        qa[k] = (qx1[k] - qx0[k]) * (qy1[k] - qy0[k]);
    }

    const float* sp = scores + row0 * C;       // row k at sp + k*C (imm)
    float* op = out + (size_t)row0 * M + tx;   // store at op + k*M + jj*64 (imm)
    const float4* tb = tboxes + tx;
    const int* lb = g_lab + tx;

#pragma unroll
    for (int jj = 0; jj < NJ; jj++) {
        float4 b = __ldg(tb + jj * 64);        // target cxcywh
        int lab = __ldg(lb + jj * 64);
        float hw = 0.5f * b.z, hh = 0.5f * b.w;
        float tx0 = b.x - hw, ty0 = b.y - hh;
        float tx1 = b.x + hw, ty1 = b.y + hh;
        float ta = (tx1 - tx0) * (ty1 - ty0);
        const float* sa = sp + lab;

#pragma unroll
        for (int k = 0; k < 4; k++) {
            float sc = __ldg(sa + k * C);      // immediate-offset gather

            // L1 on cxcywh, rebuilt from xyxy diffs:
            // |cx-cx'| = 0.5|dx0+dx1|, |w-w'| = |dx1-dx0|
            float dx0 = qx0[k] - tx0, dy0 = qy0[k] - ty0;
            float dx1 = qx1[k] - tx1, dy1 = qy1[k] - ty1;
            float sA = fabsf(dx0 + dx1) + fabsf(dy0 + dy1);
            float sB = fabsf(dx1 - dx0) + fabsf(dy1 - dy0);
            float l1 = fmaf(0.5f, sA, sB);

            // intersection
            float ltx = fmaxf(qx0[k], tx0), lty = fmaxf(qy0[k], ty0);
            float rbx = fminf(qx1[k], tx1), rby = fminf(qy1[k], ty1);
            float iw = fmaxf(rbx - ltx, 0.0f), ih = fmaxf(rby - lty, 0.0f);
            float inter = iw * ih;
            float uni = qa[k] + ta - inter;

            // enclosing box
            float ex0 = fminf(qx0[k], tx0), ey0 = fminf(qy0[k], ty0);
            float ex1 = fmaxf(qx1[k], tx1), ey1 = fmaxf(qy1[k], ty1);
            float ae = (ex1 - ex0) * (ey1 - ey0);

            // cost = 5*l1 + (2 - sc) - 2*(inter/uni + uni/ae)
            float s = fmaf(uni, frcp(ae), inter * frcp(uni));
            float c = fmaf(5.0f, l1, 2.0f - sc);
            c = fmaf(-2.0f, s, c);

            op[k * M + jj * 64] = c;
        }
    }
}

// ---------------------------------------------------------------------------
// Generic fallback for unexpected shapes.
// ---------------------------------------------------------------------------
__global__ void __launch_bounds__(256)
cost_kernel(const float* __restrict__ scores,
            const float4* __restrict__ boxes,
            const float4* __restrict__ tboxes,
            float* __restrict__ out,
            int rows, int C, int m) {
    int tid = threadIdx.x;
    int tx = tid & 63;
    int ty = tid >> 6;
    int row0 = blockIdx.x * 16 + ty * 4;

    float qcx[4], qcy[4], qw[4], qh[4];
    float qx0[4], qy0[4], qx1[4], qy1[4], qa[4];
    const float* srow[4];
    float* orow[4];

#pragma unroll
    for (int k = 0; k < 4; k++) {
        int r = row0 + k;
        if (r > rows - 1) r = rows - 1;
        float4 bb = __ldg(boxes + r);
        qcx[k] = bb.x; qcy[k] = bb.y; qw[k] = bb.z; qh[k] = bb.w;
        float hw = 0.5f * bb.z, hh = 0.5f * bb.w;
        qx0[k] = bb.x - hw; qy0[k] = bb.y - hh;
        qx1[k] = bb.x + hw; qy1[k] = bb.y + hh;
        qa[k] = (qx1[k] - qx0[k]) * (qy1[k] - qy0[k]);
        srow[k] = scores + (size_t)r * C;
        orow[k] = out + (size_t)r * m + tx;
    }

    int nj = (m + 63) >> 6;
    for (int jj = 0; jj < nj; jj++) {
        int j = tx + (jj << 6);
        if (j >= m) break;
        float4 t  = __ldg(g_txyxy + j);
        float4 tc = __ldg(tboxes + j);
        float2 al = __ldg(g_tal + j);
        float ta = al.x;
        int lab = __float_as_int(al.y);

#pragma unroll
        for (int k = 0; k < 4; k++) {
            float sc = __ldg(srow[k] + lab);
            float l1 = fabsf(qcx[k] - tc.x) + fabsf(qcy[k] - tc.y)
                     + fabsf(qw[k] - tc.z) + fabsf(qh[k] - tc.w);
            float ltx = fmaxf(qx0[k], t.x), lty = fmaxf(qy0[k], t.y);
            float rbx = fminf(qx1[k], t.z), rby = fminf(qy1[k], t.w);
            float iw = fmaxf(rbx - ltx, 0.0f), ih = fmaxf(rby - lty, 0.0f);
            float inter = iw * ih;
            float uni = qa[k] + ta - inter;
            float ex0 = fminf(qx0[k], t.x), ey0 = fminf(qy0[k], t.y);
            float ex1 = fmaxf(qx1[k], t.z), ey1 = fmaxf(qy1[k], t.w);
            float ae = (ex1 - ex0) * (ey1 - ey0);
            float s = fmaf(uni, frcp(ae), inter * frcp(uni));
            float c = fmaf(5.0f, l1, 2.0f - sc);
            c = fmaf(-2.0f, s, c);
            orow[k][(size_t)(jj << 6)] = c;
        }
    }
}

extern "C" void kernel_launch(void* const* d_in, const int* in_sizes, int n_in,
                              void* d_out, int out_size) {
    const float* scores  = (const float*)d_in[0];
    const float4* boxes  = (const float4*)d_in[1];
    const int*   labraw  = (const int*)d_in[2];
    const float4* tboxes = (const float4*)d_in[3];
    float* out = (float*)d_out;

    int rows = in_sizes[1] / 4;      // b*n = 9600
    int m    = in_sizes[3] / 4;      // 1280
    int C    = in_sizes[0] / rows;   // 91

    setup_kernel<<<1, 512>>>(tboxes, labraw, m);

    if (C == 91 && m == 1280 && (rows % 16) == 0) {
        cost_kernel_fast<<<rows / 16, 256>>>(scores, boxes, tboxes, out);
    } else {
        int blocks = (rows + 15) / 16;
        cost_kernel<<<blocks, 256>>>(scores, boxes, tboxes, out, rows, C, m);
    }
}

// round 4
// speedup vs baseline: 1.0832x; 1.0832x over previous
#include <cuda_runtime.h>
#include <cstdint>

#define TMAX 1280

__device__ int g_lab[TMAX];        // fallback path only
__device__ float4 g_txyxy[TMAX];   // fallback path only
__device__ float2 g_tal[TMAX];     // fallback path only

__device__ __forceinline__ float frcp(float x) {
    float r;
    asm("rcp.approx.f32 %0, %1;" : "=f"(r) : "f"(x));
    return r;
}

// Fallback-path setup: normalizes labels (int64/int32 autodetect) and
// precomputes target xyxy + area.
__global__ void setup_kernel(const float4* __restrict__ tboxes,
                             const int* __restrict__ lraw, int m) {
    __shared__ int is64;
    if (threadIdx.x == 0) is64 = 1;
    __syncthreads();
    for (int t = threadIdx.x; t < m / 2; t += blockDim.x)
        if (lraw[2 * t + 1] != 0) is64 = 0;   // benign race, single value
    __syncthreads();
    int f = is64;
    for (int j = threadIdx.x; j < m; j += blockDim.x) {
        int lab = f ? lraw[2 * j] : lraw[j];
        g_lab[j] = lab;
        float4 b = tboxes[j];
        float hw = 0.5f * b.z, hh = 0.5f * b.w;
        float4 t;
        t.x = b.x - hw; t.y = b.y - hh;
        t.z = b.x + hw; t.w = b.y + hh;
        g_txyxy[j] = t;
        float2 al;
        al.x = (t.z - t.x) * (t.w - t.y);
        al.y = __int_as_float(lab);
        g_tal[j] = al;
    }
}

// ---------------------------------------------------------------------------
// Fast path, specialized: C=91, M=1280, rows % 16 == 0. Single launch.
// Block = 256 thr = 16 rows x 64 column-lanes; thread owns 4 rows x 20 steps.
// Row state: qx0,qy0,qx1,qy1,qwx,qwy (6 regs/row).
// Enclosing box via identity ew = (qwx+twx) - o_x, reusing overlap o_x.
// ---------------------------------------------------------------------------
__global__ void __launch_bounds__(256, 4)
cost_kernel_fast(const float* __restrict__ scores,
                 const float4* __restrict__ boxes,
                 const int* __restrict__ lraw,
                 const float4* __restrict__ tboxes,
                 float* __restrict__ out) {
    constexpr int C = 91;
    constexpr int M = 1280;
    constexpr int NJ = M / 64;   // 20

    int tid = threadIdx.x;
    int tx = tid & 63;
    int ty = tid >> 6;
    int row0 = blockIdx.x * 16 + ty * 4;

    // In-block label-width probe: int64 labels (<2^31) have zero high words.
    __shared__ int s_is64;
    if (tid == 0) s_is64 = 1;
    __syncthreads();
#pragma unroll 1
    for (int t = tid; t < M / 2; t += 256)
        if (lraw[2 * t + 1] != 0) s_is64 = 0;

    float qx0[4], qy0[4], qx1[4], qy1[4], qwx[4], qwy[4];
#pragma unroll
    for (int k = 0; k < 4; k++) {
        float4 bb = __ldg(boxes + row0 + k);
        float hw = 0.5f * bb.z, hh = 0.5f * bb.w;
        qx0[k] = bb.x - hw; qy0[k] = bb.y - hh;
        qx1[k] = bb.x + hw; qy1[k] = bb.y + hh;
        qwx[k] = qx1[k] - qx0[k];
        qwy[k] = qy1[k] - qy0[k];
    }
    __syncthreads();
    int sh = s_is64;                       // 1 -> int64 stride, 0 -> int32

    const float* sp = scores + row0 * C;   // row k at sp + k*C (imm)
    float* op = out + (size_t)row0 * M + tx;
    const float4* tb = tboxes + tx;
    const int* lp = lraw + (tx << sh);
    int lstride = 64 << sh;

#pragma unroll
    for (int jj = 0; jj < NJ; jj++) {
        float4 b = __ldg(tb + jj * 64);            // target cxcywh
        int lab = __ldg(lp + jj * lstride);        // label gather
        float hw = 0.5f * b.z, hh = 0.5f * b.w;
        float tx0 = b.x - hw, ty0 = b.y - hh;
        float tx1 = b.x + hw, ty1 = b.y + hh;
        float twx = tx1 - tx0, twy = ty1 - ty0;    // xyxy-derived widths
        float ta = twx * twy;
        const float* sa = sp + lab;

        float scv[4];
#pragma unroll
        for (int k = 0; k < 4; k++) scv[k] = __ldg(sa + k * C);

#pragma unroll
        for (int k = 0; k < 4; k++) {
            // L1 on cxcywh from xyxy diffs:
            // |dcx| = 0.5|dx0+dx1|, |dw| = |dx1-dx0|
            float dx0 = qx0[k] - tx0, dy0 = qy0[k] - ty0;
            float dx1 = qx1[k] - tx1, dy1 = qy1[k] - ty1;
            float sA = fabsf(dx0 + dx1) + fabsf(dy0 + dy1);
            float sB = fabsf(dx1 - dx0) + fabsf(dy1 - dy0);
            float l1 = fmaf(0.5f, sA, sB);

            // signed overlap per dim (reused for both inter and enclosure)
            float ox = fminf(qx1[k], tx1) - fmaxf(qx0[k], tx0);
            float oy = fminf(qy1[k], ty1) - fmaxf(qy0[k], ty0);
            float iw = fmaxf(ox, 0.0f), ih = fmaxf(oy, 0.0f);
            float inter = iw * ih;

            // enclosing box: max(hi)-min(lo) == w1 + w2 - signed_overlap
            float ew = (qwx[k] + twx) - ox;
            float eh = (qwy[k] + twy) - oy;
            float ae = ew * eh;

            float uni = fmaf(qwx[k], qwy[k], ta) - inter;

            // cost = 5*l1 + (2 - sc) - 2*(inter/uni + uni/ae)
            float s = fmaf(uni, frcp(ae), inter * frcp(uni));
            float c = fmaf(5.0f, l1, 2.0f - scv[k]);
            c = fmaf(-2.0f, s, c);

            op[k * M + jj * 64] = c;
        }
    }
}

// ---------------------------------------------------------------------------
// Generic fallback for unexpected shapes.
// ---------------------------------------------------------------------------
__global__ void __launch_bounds__(256)
cost_kernel(const float* __restrict__ scores,
            const float4* __restrict__ boxes,
            const float4* __restrict__ tboxes,
            float* __restrict__ out,
            int rows, int C, int m) {
    int tid = threadIdx.x;
    int tx = tid & 63;
    int ty = tid >> 6;
    int row0 = blockIdx.x * 16 + ty * 4;

    float qcx[4], qcy[4], qw[4], qh[4];
    float qx0[4], qy0[4], qx1[4], qy1[4], qa[4];
    const float* srow[4];
    float* orow[4];

#pragma unroll
    for (int k = 0; k < 4; k++) {
        int r = row0 + k;
        if (r > rows - 1) r = rows - 1;
        float4 bb = __ldg(boxes + r);
        qcx[k] = bb.x; qcy[k] = bb.y; qw[k] = bb.z; qh[k] = bb.w;
        float hw = 0.5f * bb.z, hh = 0.5f * bb.w;
        qx0[k] = bb.x - hw; qy0[k] = bb.y - hh;
        qx1[k] = bb.x + hw; qy1[k] = bb.y + hh;
        qa[k] = (qx1[k] - qx0[k]) * (qy1[k] - qy0[k]);
        srow[k] = scores + (size_t)r * C;
        orow[k] = out + (size_t)r * m + tx;
    }

    int nj = (m + 63) >> 6;
    for (int jj = 0; jj < nj; jj++) {
        int j = tx + (jj << 6);
        if (j >= m) break;
        float4 t  = __ldg(g_txyxy + j);
        float4 tc = __ldg(tboxes + j);
        float2 al = __ldg(g_tal + j);
        float ta = al.x;
        int lab = __float_as_int(al.y);

#pragma unroll
        for (int k = 0; k < 4; k++) {
            float sc = __ldg(srow[k] + lab);
            float l1 = fabsf(qcx[k] - tc.x) + fabsf(qcy[k] - tc.y)
                     + fabsf(qw[k] - tc.z) + fabsf(qh[k] - tc.w);
            float ltx = fmaxf(qx0[k], t.x), lty = fmaxf(qy0[k], t.y);
            float rbx = fminf(qx1[k], t.z), rby = fminf(qy1[k], t.w);
            float iw = fmaxf(rbx - ltx, 0.0f), ih = fmaxf(rby - lty, 0.0f);
            float inter = iw * ih;
            float uni = qa[k] + ta - inter;
            float ex0 = fminf(qx0[k], t.x), ey0 = fminf(qy0[k], t.y);
            float ex1 = fmaxf(qx1[k], t.z), ey1 = fmaxf(qy1[k], t.w);
            float ae = (ex1 - ex0) * (ey1 - ey0);
            float s = fmaf(uni, frcp(ae), inter * frcp(uni));
            float c = fmaf(5.0f, l1, 2.0f - sc);
            c = fmaf(-2.0f, s, c);
            orow[k][(size_t)(jj << 6)] = c;
        }
    }
}

extern "C" void kernel_launch(void* const* d_in, const int* in_sizes, int n_in,
                              void* d_out, int out_size) {
    const float* scores  = (const float*)d_in[0];
    const float4* boxes  = (const float4*)d_in[1];
    const int*   labraw  = (const int*)d_in[2];
    const float4* tboxes = (const float4*)d_in[3];
    float* out = (float*)d_out;

    int rows = in_sizes[1] / 4;      // b*n = 9600
    int m    = in_sizes[3] / 4;      // 1280
    int C    = in_sizes[0] / rows;   // 91

    if (C == 91 && m == 1280 && (rows % 16) == 0) {
        cost_kernel_fast<<<rows / 16, 256>>>(scores, boxes, labraw, tboxes, out);
    } else {
        setup_kernel<<<1, 512>>>(tboxes, labraw, m);
        int blocks = (rows + 15) / 16;
        cost_kernel<<<blocks, 256>>>(scores, boxes, tboxes, out, rows, C, m);
    }
}